// round 7
// baseline (speedup 1.0000x reference)
#include <cuda_runtime.h>
#include <cuda_fp16.h>
#include <cstdint>

// Problem constants
#define B_   16
#define C_   128
#define H_   128
#define W_   128
#define OUT_ 256
#define HW_  (H_ * W_)

#define KSTR 136   // halves per Ys row (272 B); conflict-free ldmatrix rows

// Shared memory layout (bytes):
//  [0      : 34816)   Ys0  half[128][136]
//  [34816  : 69632)   Ys1  half[128][136]
//  [69632  : 135168)  A fragments (fp16 packed), 64 KB
//  [135168 : 168960)  D stage, float[64][132]
#define SMEM_YS   34816
#define SMEM_A    (2 * SMEM_YS)            // 69632
#define SMEM_D    (SMEM_A + 65536)         // 135168
#define DSTR      132
#define SMEM_TOT  (SMEM_D + 64 * DSTR * 4) // 168960

// Pre-packed W as fp16 A-fragments for mma.m16n8k16:
//   g_AF[kstep 8][mtile 16][lane 32][reg 4]  (uint32 = half2)
__device__ uint32_t g_AF[8 * 16 * 32 * 4];   // 64 KB

__device__ __forceinline__ uint32_t s2u(const void* p) {
    uint32_t a;
    asm("{ .reg .u64 t; cvta.to.shared.u64 t, %1; cvt.u32.u64 %0, t; }" : "=r"(a) : "l"(p));
    return a;
}

__device__ __forceinline__ void mma_f16(float* d, const uint32_t* a, const uint32_t* b) {
    asm volatile(
        "mma.sync.aligned.m16n8k16.row.col.f32.f16.f16.f32 "
        "{%0,%1,%2,%3}, {%4,%5,%6,%7}, {%8,%9}, {%0,%1,%2,%3};"
        : "+f"(d[0]), "+f"(d[1]), "+f"(d[2]), "+f"(d[3])
        : "r"(a[0]), "r"(a[1]), "r"(a[2]), "r"(a[3]), "r"(b[0]), "r"(b[1]));
}

// ---------------------------------------------------------------------------
// Prep kernel: pack W (OUT x C, f32) into fp16 fragment image g_AF.
// ---------------------------------------------------------------------------
__global__ __launch_bounds__(512) void prep_kernel(const float* __restrict__ Wg) {
    const int idx   = blockIdx.x * 512 + threadIdx.x;   // 0..16383
    const int r     = idx & 3;
    const int lane  = (idx >> 2) & 31;
    const int mtile = (idx >> 7) & 15;
    const int kstep = idx >> 11;
    const int m = mtile * 16 + (lane >> 2) + ((r & 1) << 3);
    const int k = kstep * 16 + ((lane & 3) << 1) + ((r >> 1) << 3);
    const __half2 h = __floats2half2_rn(Wg[m * C_ + k], Wg[m * C_ + k + 1]);
    g_AF[idx] = *(const uint32_t*)&h;
}

// ---------------------------------------------------------------------------
// Fused kernel: one CTA per (b, h-pair). 512 threads = 16 warps (4M x 4N).
//   Phase 0: cp.async A-fragment image (64 KB)
//   Phase 1: merged depthwise for rows h0, h0+1 (4 x-row loads) -> Ys0, Ys1
//   Phase 2: per row: fp16 GEMM m16n8k16 -> staged coalesced epilogue
// ---------------------------------------------------------------------------
__global__ __launch_bounds__(512, 1) void fused_kernel(
    const float* __restrict__ x,
    const float* __restrict__ colk,
    const float* __restrict__ rowk,
    float* __restrict__ out)
{
    extern __shared__ char smem[];
    const uint32_t sb = s2u(smem);

    const int tid  = threadIdx.x;
    const int lane = tid & 31;
    const int warp = tid >> 5;
    const int h0   = blockIdx.x * 2;
    const int b    = blockIdx.y;

    // ---------------- Phase 0: cp.async A image ----------------
    {
        const size_t gsrc = __cvta_generic_to_global(g_AF) + (size_t)tid * 16;
        const uint32_t dst = sb + SMEM_A + tid * 16;
        #pragma unroll
        for (int i = 0; i < 8; ++i) {
            asm volatile("cp.async.ca.shared.global [%0], [%1], 16;"
                         :: "r"(dst + i * 512 * 16), "l"(gsrc + (size_t)i * 512 * 16)
                         : "memory");
        }
        asm volatile("cp.async.commit_group;" ::: "memory");
    }

    // ---------------- Phase 1: merged depthwise (rows h0, h0+1) ----------------
    {
        const unsigned FULL = 0xFFFFFFFFu;
        #pragma unroll
        for (int i = 0; i < 8; ++i) {
            const int c = warp * 8 + i;
            const float r0 = rowk[c * 3 + 0], r1 = rowk[c * 3 + 1], r2 = rowk[c * 3 + 2];
            const float ck0 = colk[c * 3 + 0], ck1 = colk[c * 3 + 1], ck2 = colk[c * 3 + 2];
            const float* xc = x + ((size_t)(b * C_ + c) * H_) * W_;

            float t[4][4];
            #pragma unroll
            for (int j = 0; j < 4; ++j) {
                const int row = h0 - 1 + j;
                float4 v = make_float4(0.f, 0.f, 0.f, 0.f);
                if (row >= 0 && row < H_)
                    v = *(const float4*)(xc + (size_t)row * W_ + lane * 4);
                float left  = __shfl_up_sync(FULL, v.w, 1);
                float right = __shfl_down_sync(FULL, v.x, 1);
                if (lane == 0)  left = 0.f;
                if (lane == 31) right = 0.f;
                t[j][0] = r0 * left + r1 * v.x + r2 * v.y;
                t[j][1] = r0 * v.x  + r1 * v.y + r2 * v.z;
                t[j][2] = r0 * v.y  + r1 * v.z + r2 * v.w;
                t[j][3] = r0 * v.z  + r1 * v.w + r2 * right;
            }
            #pragma unroll
            for (int row = 0; row < 2; ++row) {
                float y0 = ck0 * t[row][0] + ck1 * t[row + 1][0] + ck2 * t[row + 2][0];
                float y1 = ck0 * t[row][1] + ck1 * t[row + 1][1] + ck2 * t[row + 2][1];
                float y2 = ck0 * t[row][2] + ck1 * t[row + 1][2] + ck2 * t[row + 2][2];
                float y3 = ck0 * t[row][3] + ck1 * t[row + 1][3] + ck2 * t[row + 2][3];
                const __half2 h01 = __floats2half2_rn(y0, y1);
                const __half2 h23 = __floats2half2_rn(y2, y3);
                uint2 tw;
                tw.x = *(const uint32_t*)&h01;
                tw.y = *(const uint32_t*)&h23;
                *(uint2*)(smem + row * SMEM_YS + (size_t)c * (KSTR * 2) + lane * 8) = tw;
            }
        }
    }

    asm volatile("cp.async.wait_group 0;" ::: "memory");
    __syncthreads();

    // ---------------- Phase 2: per-row GEMM + staged epilogue ----------------
    const int wm = warp >> 2;   // 0..3
    const int wn = warp & 3;    // 0..3

    const uint32_t aBase = sb + SMEM_A + (uint32_t)(((wm * 4) * 32 + lane) * 16);
    const int bt   = lane >> 3;
    const int brow = lane & 7;
    float* Ds = (float*)(smem + SMEM_D);

    #pragma unroll 1
    for (int row = 0; row < 2; ++row) {
        const uint32_t ysBase = sb + row * SMEM_YS;

        float acc[4][4][4] = {};
        #pragma unroll
        for (int k = 0; k < 8; ++k) {
            uint32_t a[4][4];
            #pragma unroll
            for (int mt = 0; mt < 4; ++mt) {
                const uint32_t addr = aBase + (uint32_t)(k * 16 * 512 + mt * 512);
                asm volatile("ld.shared.v4.b32 {%0,%1,%2,%3}, [%4];"
                             : "=r"(a[mt][0]), "=r"(a[mt][1]), "=r"(a[mt][2]), "=r"(a[mt][3])
                             : "r"(addr));
            }
            uint32_t bf[4][2];
            #pragma unroll
            for (int q = 0; q < 2; ++q) {
                const int krow = k * 16 + (bt & 1) * 8 + brow;
                const int col  = wn * 32 + q * 16 + (bt >> 1) * 8;
                const uint32_t addr = ysBase + (uint32_t)(krow * (KSTR * 2) + col * 2);
                asm volatile("ldmatrix.sync.aligned.m8n8.x4.trans.shared.b16 "
                             "{%0,%1,%2,%3}, [%4];"
                             : "=r"(bf[q * 2][0]), "=r"(bf[q * 2][1]),
                               "=r"(bf[q * 2 + 1][0]), "=r"(bf[q * 2 + 1][1])
                             : "r"(addr));
            }
            #pragma unroll
            for (int mt = 0; mt < 4; ++mt)
                #pragma unroll
                for (int nt = 0; nt < 4; ++nt)
                    mma_f16(acc[mt][nt], a[mt], bf[nt]);
        }

        // staged epilogue: per mt, acc -> smem -> coalesced STG.128
        float* ob = out + ((size_t)b * OUT_) * HW_ + (size_t)(h0 + row) * W_;
        #pragma unroll 1
        for (int mt = 0; mt < 4; ++mt) {
            __syncthreads();    // protect previous stage's reads
            #pragma unroll
            for (int nt = 0; nt < 4; ++nt) {
                const int p = wn * 32 + nt * 8 + (lane & 3) * 2;
                const int dr = wm * 16 + (lane >> 2);
                *(float2*)&Ds[dr * DSTR + p] =
                    make_float2(acc[mt][nt][0], acc[mt][nt][1]);
                *(float2*)&Ds[(dr + 8) * DSTR + p] =
                    make_float2(acc[mt][nt][2], acc[mt][nt][3]);
            }
            __syncthreads();
            #pragma unroll
            for (int rr = 0; rr < 4; ++rr) {
                const int dsrow = warp * 4 + rr;
                const float4 val = *(const float4*)&Ds[dsrow * DSTR + lane * 4];
                const int o = (dsrow >> 4) * 64 + mt * 16 + (dsrow & 15);
                *(float4*)(ob + (size_t)o * HW_ + lane * 4) = val;
            }
        }
        __syncthreads();        // Ds reads done before next row reuses it
    }
}

// ---------------------------------------------------------------------------
extern "C" void kernel_launch(void* const* d_in, const int* in_sizes, int n_in,
                              void* d_out, int out_size)
{
    (void)in_sizes; (void)n_in; (void)out_size;
    const float* x    = (const float*)d_in[0];
    const float* colk = (const float*)d_in[1];
    const float* rowk = (const float*)d_in[2];
    const float* pw   = (const float*)d_in[3];
    float* out = (float*)d_out;

    prep_kernel<<<32, 512>>>(pw);
    cudaFuncSetAttribute(fused_kernel, cudaFuncAttributeMaxDynamicSharedMemorySize, SMEM_TOT);
    fused_kernel<<<dim3(H_ / 2, B_), 512, SMEM_TOT>>>(x, colk, rowk, out);
}

// round 9
// speedup vs baseline: 1.4932x; 1.4932x over previous
#include <cuda_runtime.h>
#include <cuda_fp16.h>
#include <cstdint>

// Problem constants
#define B_   16
#define C_   128
#define H_   128
#define W_   128
#define OUT_ 256
#define HW_  (H_ * W_)

#define KSTR 136   // halves per Ys row (272 B); conflict-free ldmatrix rows

// Shared memory layout (bytes):
//  [0      : 34816)   Ys0  half[128][136]
//  [34816  : 69632)   Ys1  half[128][136]
//  [69632  : 135168)  A fragments (fp16 packed), 64 KB
//  [135168 : 172032)  per-warp store stage: 16 warps x (16 x 36 floats)
#define SMEM_YS   34816
#define SMEM_A    (2 * SMEM_YS)              // 69632
#define SMEM_STG  (SMEM_A + 65536)           // 135168
#define DSTR      36                          // 144 B row stride: 16B-aligned float4 rows
#define STG_WORDS (16 * DSTR)                 // 576 floats / warp
#define SMEM_TOT  (SMEM_STG + 16 * STG_WORDS * 4)   // 172032

// Pre-packed W as fp16 A-fragments for mma.m16n8k16:
//   g_AF[kstep 8][mtile 16][lane 32][reg 4]  (uint32 = half2)
__device__ uint32_t g_AF[8 * 16 * 32 * 4];   // 64 KB

__device__ __forceinline__ uint32_t s2u(const void* p) {
    uint32_t a;
    asm("{ .reg .u64 t; cvta.to.shared.u64 t, %1; cvt.u32.u64 %0, t; }" : "=r"(a) : "l"(p));
    return a;
}

__device__ __forceinline__ void mma_f16(float* d, const uint32_t* a, const uint32_t* b) {
    asm volatile(
        "mma.sync.aligned.m16n8k16.row.col.f32.f16.f16.f32 "
        "{%0,%1,%2,%3}, {%4,%5,%6,%7}, {%8,%9}, {%0,%1,%2,%3};"
        : "+f"(d[0]), "+f"(d[1]), "+f"(d[2]), "+f"(d[3])
        : "r"(a[0]), "r"(a[1]), "r"(a[2]), "r"(a[3]), "r"(b[0]), "r"(b[1]));
}

// ---------------------------------------------------------------------------
// Prep kernel: pack W (OUT x C, f32) into fp16 fragment image g_AF.
// ---------------------------------------------------------------------------
__global__ __launch_bounds__(512) void prep_kernel(const float* __restrict__ Wg) {
    const int idx   = blockIdx.x * 512 + threadIdx.x;   // 0..16383
    const int r     = idx & 3;
    const int lane  = (idx >> 2) & 31;
    const int mtile = (idx >> 7) & 15;
    const int kstep = idx >> 11;
    const int m = mtile * 16 + (lane >> 2) + ((r & 1) << 3);
    const int k = kstep * 16 + ((lane & 3) << 1) + ((r >> 1) << 3);
    const __half2 h = __floats2half2_rn(Wg[m * C_ + k], Wg[m * C_ + k + 1]);
    g_AF[idx] = *(const uint32_t*)&h;
}

// ---------------------------------------------------------------------------
// Fused kernel: one CTA per (b, h-pair). 512 threads = 16 warps (4M x 4N).
//   Phase 0: cp.async A-fragment image (64 KB)
//   Phase 1: merged depthwise for rows h0, h0+1 (4 x-row loads) -> Ys0, Ys1
//   Phase 2: per row fp16 GEMM m16n8k16; per-warp staged coalesced epilogue
//            (only ONE CTA-wide barrier in the whole kernel)
// ---------------------------------------------------------------------------
__global__ __launch_bounds__(512, 1) void fused_kernel(
    const float* __restrict__ x,
    const float* __restrict__ colk,
    const float* __restrict__ rowk,
    float* __restrict__ out)
{
    extern __shared__ char smem[];
    const uint32_t sb = s2u(smem);

    const int tid  = threadIdx.x;
    const int lane = tid & 31;
    const int warp = tid >> 5;
    const int h0   = blockIdx.x * 2;
    const int b    = blockIdx.y;

    // ---------------- Phase 0: cp.async A image ----------------
    {
        const size_t gsrc = __cvta_generic_to_global(g_AF) + (size_t)tid * 16;
        const uint32_t dst = sb + SMEM_A + tid * 16;
        #pragma unroll
        for (int i = 0; i < 8; ++i) {
            asm volatile("cp.async.ca.shared.global [%0], [%1], 16;"
                         :: "r"(dst + i * 512 * 16), "l"(gsrc + (size_t)i * 512 * 16)
                         : "memory");
        }
        asm volatile("cp.async.commit_group;" ::: "memory");
    }

    // ---------------- Phase 1: merged depthwise (rows h0, h0+1) ----------------
    {
        const unsigned FULL = 0xFFFFFFFFu;
        #pragma unroll
        for (int i = 0; i < 8; ++i) {
            const int c = warp * 8 + i;
            const float r0 = rowk[c * 3 + 0], r1 = rowk[c * 3 + 1], r2 = rowk[c * 3 + 2];
            const float ck0 = colk[c * 3 + 0], ck1 = colk[c * 3 + 1], ck2 = colk[c * 3 + 2];
            const float* xc = x + ((size_t)(b * C_ + c) * H_) * W_;

            float t[4][4];
            #pragma unroll
            for (int j = 0; j < 4; ++j) {
                const int row = h0 - 1 + j;
                float4 v = make_float4(0.f, 0.f, 0.f, 0.f);
                if (row >= 0 && row < H_)
                    v = *(const float4*)(xc + (size_t)row * W_ + lane * 4);
                float left  = __shfl_up_sync(FULL, v.w, 1);
                float right = __shfl_down_sync(FULL, v.x, 1);
                if (lane == 0)  left = 0.f;
                if (lane == 31) right = 0.f;
                t[j][0] = r0 * left + r1 * v.x + r2 * v.y;
                t[j][1] = r0 * v.x  + r1 * v.y + r2 * v.z;
                t[j][2] = r0 * v.y  + r1 * v.z + r2 * v.w;
                t[j][3] = r0 * v.z  + r1 * v.w + r2 * right;
            }
            #pragma unroll
            for (int row = 0; row < 2; ++row) {
                float y0 = ck0 * t[row][0] + ck1 * t[row + 1][0] + ck2 * t[row + 2][0];
                float y1 = ck0 * t[row][1] + ck1 * t[row + 1][1] + ck2 * t[row + 2][1];
                float y2 = ck0 * t[row][2] + ck1 * t[row + 1][2] + ck2 * t[row + 2][2];
                float y3 = ck0 * t[row][3] + ck1 * t[row + 1][3] + ck2 * t[row + 2][3];
                const __half2 h01 = __floats2half2_rn(y0, y1);
                const __half2 h23 = __floats2half2_rn(y2, y3);
                uint2 tw;
                tw.x = *(const uint32_t*)&h01;
                tw.y = *(const uint32_t*)&h23;
                *(uint2*)(smem + row * SMEM_YS + (size_t)c * (KSTR * 2) + lane * 8) = tw;
            }
        }
    }

    asm volatile("cp.async.wait_group 0;" ::: "memory");
    __syncthreads();                       // the only CTA-wide barrier

    // ---------------- Phase 2: per-row GEMM + per-warp staged epilogue --------
    const int wm = warp >> 2;   // 0..3
    const int wn = warp & 3;    // 0..3

    const uint32_t aBase = sb + SMEM_A + (uint32_t)(((wm * 4) * 32 + lane) * 16);
    const int bt   = lane >> 3;
    const int brow = lane & 7;
    float* stage = (float*)(smem + SMEM_STG) + warp * STG_WORDS;

    #pragma unroll 1
    for (int row = 0; row < 2; ++row) {
        const uint32_t ysBase = sb + row * SMEM_YS;

        float acc[4][4][4] = {};
        #pragma unroll
        for (int k = 0; k < 8; ++k) {
            uint32_t a[4][4];
            #pragma unroll
            for (int mt = 0; mt < 4; ++mt) {
                const uint32_t addr = aBase + (uint32_t)(k * 16 * 512 + mt * 512);
                asm volatile("ld.shared.v4.b32 {%0,%1,%2,%3}, [%4];"
                             : "=r"(a[mt][0]), "=r"(a[mt][1]), "=r"(a[mt][2]), "=r"(a[mt][3])
                             : "r"(addr));
            }
            uint32_t bf[4][2];
            #pragma unroll
            for (int q = 0; q < 2; ++q) {
                const int krow = k * 16 + (bt & 1) * 8 + brow;
                const int col  = wn * 32 + q * 16 + (bt >> 1) * 8;
                const uint32_t addr = ysBase + (uint32_t)(krow * (KSTR * 2) + col * 2);
                asm volatile("ldmatrix.sync.aligned.m8n8.x4.trans.shared.b16 "
                             "{%0,%1,%2,%3}, [%4];"
                             : "=r"(bf[q * 2][0]), "=r"(bf[q * 2][1]),
                               "=r"(bf[q * 2 + 1][0]), "=r"(bf[q * 2 + 1][1])
                             : "r"(addr));
            }
            #pragma unroll
            for (int mt = 0; mt < 4; ++mt)
                #pragma unroll
                for (int nt = 0; nt < 4; ++nt)
                    mma_f16(acc[mt][nt], a[mt], bf[nt]);
        }

        // per-warp staged epilogue: acc(16x32) -> stage -> 4x STG.128 per pass
        float* ob = out + ((size_t)b * OUT_) * HW_ + (size_t)(h0 + row) * W_ + wn * 32;
        #pragma unroll
        for (int mt = 0; mt < 4; ++mt) {
            __syncwarp();
            #pragma unroll
            for (int nt = 0; nt < 4; ++nt) {
                const int p  = nt * 8 + (lane & 3) * 2;
                const int dr = lane >> 2;
                *(float2*)&stage[dr * DSTR + p] =
                    make_float2(acc[mt][nt][0], acc[mt][nt][1]);
                *(float2*)&stage[(dr + 8) * DSTR + p] =
                    make_float2(acc[mt][nt][2], acc[mt][nt][3]);
            }
            __syncwarp();
            #pragma unroll
            for (int rr = 0; rr < 4; ++rr) {
                const int r4   = rr * 4 + (lane >> 3);       // 0..15
                const int colf = (lane & 7) * 4;
                const float4 v = *(const float4*)&stage[r4 * DSTR + colf];
                const int o = wm * 64 + mt * 16 + r4;
                *(float4*)(ob + (size_t)o * HW_ + colf) = v;
            }
        }
    }
}

// ---------------------------------------------------------------------------
extern "C" void kernel_launch(void* const* d_in, const int* in_sizes, int n_in,
                              void* d_out, int out_size)
{
    (void)in_sizes; (void)n_in; (void)out_size;
    const float* x    = (const float*)d_in[0];
    const float* colk = (const float*)d_in[1];
    const float* rowk = (const float*)d_in[2];
    const float* pw   = (const float*)d_in[3];
    float* out = (float*)d_out;

    prep_kernel<<<32, 512>>>(pw);
    cudaFuncSetAttribute(fused_kernel, cudaFuncAttributeMaxDynamicSharedMemorySize, SMEM_TOT);
    fused_kernel<<<dim3(H_ / 2, B_), 512, SMEM_TOT>>>(x, colk, rowk, out);
}